// round 12
// baseline (speedup 1.0000x reference)
#include <cuda_runtime.h>
#include <cstdint>
#include <cstddef>
#include <math.h>

#define LVL   3
#define BSZ   128
#define T0    256
#define STOCH 128
#define DETER 1024
#define EMBED 512
#define OBS_D 512
#define G3    (3*DETER)   // 3072
#define NB    128          // persistent grid (<=148 SMs, all co-resident)

typedef unsigned long long u64;

// ---------------------------------------------------------------------------
// Static device scratch (no allocations allowed).
// Transposed activations: X_T[k][m] (m contiguous, 128 floats per row).
// ---------------------------------------------------------------------------
__device__ __align__(16) float g_hT [EMBED * BSZ];
__device__ __align__(16) float g_qhT[EMBED * BSZ];
__device__ __align__(16) float g_detT[2][DETER * BSZ];   // ping-pong by t&1
__device__ float g_dets1[BSZ * 64 * DETER];     // level-1 dets (std layout)
__device__ float g_dets2[BSZ * 16 * DETER];     // level-2 dets (std layout)
__device__ float g_pre_ctx[BSZ * 64 * EMBED];   // ctx @ Wp_ctx
__device__ float g_pre_obs[BSZ * T0 * EMBED];   // obs @ Wq_obs
__device__ float g_Wcomb[EMBED * EMBED];        // Wqm @ Wp_sample (std layout)
__device__ float g_bvec[EMBED];                 // bp + bqm @ Wp_sample
// Duplicated {w,w} pairs, chunk-tiled in exact smem-consumption order.
__device__ __align__(16) float g_Wih_d[EMBED * G3 * 2];     // 12.6 MB
__device__ __align__(16) float g_Whh_d[DETER * G3 * 2];     // 25.2 MB
__device__ __align__(16) float g_Wq_d [DETER * EMBED * 2];  //  4.2 MB
__device__ __align__(16) float g_Wc_d [EMBED * EMBED * 2];  //  2.1 MB
__device__ unsigned int g_bar_count;
__device__ unsigned int g_bar_gen;

// ---------------------------------------------------------------------------
// Packed fp32 FMA (bit-exact fp32) + cp.async helpers
// ---------------------------------------------------------------------------
__device__ __forceinline__ void ffma2(u64& d, u64 a, u64 b) {
    asm("fma.rn.f32x2 %0, %1, %2, %0;" : "+l"(d) : "l"(a), "l"(b));
}
__device__ __forceinline__ float2 unpack2(u64 v) {
    float lo, hi;
    asm("mov.b64 {%0, %1}, %2;" : "=f"(lo), "=f"(hi) : "l"(v));
    return make_float2(lo, hi);
}
__device__ __forceinline__ void cp16(float* s, const float* g) {
    unsigned a = (unsigned)__cvta_generic_to_shared(s);
    asm volatile("cp.async.cg.shared.global [%0], [%1], 16;" :: "r"(a), "l"(g));
}
__device__ __forceinline__ void cp_commit() { asm volatile("cp.async.commit_group;"); }
__device__ __forceinline__ void cp_wait0()  { asm volatile("cp.async.wait_group 0;"); }
__device__ __forceinline__ void cp_wait1()  { asm volatile("cp.async.wait_group 1;"); }

// ---------------------------------------------------------------------------
// Software grid barrier. NB blocks all co-resident.
// ---------------------------------------------------------------------------
__device__ __forceinline__ void grid_sync() {
    __syncthreads();
    if (threadIdx.x == 0) {
        volatile unsigned int* genp = &g_bar_gen;
        unsigned int g = *genp;
        __threadfence();
        unsigned int a = atomicAdd(&g_bar_count, 1u);
        if (a == NB - 1u) {
            atomicExch(&g_bar_count, 0u);
            __threadfence();
            atomicAdd(&g_bar_gen, 1u);
        } else {
            while (*genp == g) { }
        }
        __threadfence();
    }
    __syncthreads();
}

// ---------------------------------------------------------------------------
// Precompute GEMM: C[M,N] = A[M,K] @ W[K,N]
// ---------------------------------------------------------------------------
__global__ __launch_bounds__(128) void gemm64_kernel(
    const float* __restrict__ A, int lda,
    const float* __restrict__ W, int ldw,
    float* __restrict__ C, int ldc, int K)
{
    constexpr int BM = 64, BN = 64, BK = 16, TM = 4, TN = 8;
    __shared__ float sA[BK][BM + 4];
    __shared__ float sW[BK][BN];

    const int tid  = threadIdx.x;
    const int tx   = tid & 7;
    const int ty   = tid >> 3;
    const int row0 = blockIdx.y * BM;
    const int col0 = blockIdx.x * BN;

    float acc[TM][TN];
    #pragma unroll
    for (int i = 0; i < TM; i++)
        #pragma unroll
        for (int j = 0; j < TN; j++) acc[i][j] = 0.0f;

    for (int k0 = 0; k0 < K; k0 += BK) {
        #pragma unroll
        for (int p = 0; p < 8; p++) {
            int i  = tid + p * 128;
            int kk = i & 15, r = i >> 4;
            sA[kk][r] = A[(size_t)(row0 + r) * lda + (k0 + kk)];
        }
        #pragma unroll
        for (int p = 0; p < 8; p++) {
            int i  = tid + p * 128;
            int kk = i >> 6, cc = i & 63;
            sW[kk][cc] = W[(size_t)(k0 + kk) * ldw + (col0 + cc)];
        }
        __syncthreads();
        #pragma unroll
        for (int kk = 0; kk < BK; kk++) {
            float4 av = *(const float4*)&sA[kk][ty * TM];
            float4 w0 = *(const float4*)&sW[kk][tx * TN];
            float4 w1 = *(const float4*)&sW[kk][tx * TN + 4];
            float a[TM] = {av.x, av.y, av.z, av.w};
            float w[TN] = {w0.x, w0.y, w0.z, w0.w, w1.x, w1.y, w1.z, w1.w};
            #pragma unroll
            for (int i = 0; i < TM; i++)
                #pragma unroll
                for (int j = 0; j < TN; j++)
                    acc[i][j] = fmaf(a[i], w[j], acc[i][j]);
        }
        __syncthreads();
    }

    #pragma unroll
    for (int i = 0; i < TM; i++) {
        int m  = row0 + ty * TM + i;
        int n0 = col0 + tx * TN;
        float4 o0 = {acc[i][0], acc[i][1], acc[i][2], acc[i][3]};
        float4 o1 = {acc[i][4], acc[i][5], acc[i][6], acc[i][7]};
        *(float4*)&C[(size_t)m * ldc + n0]     = o0;
        *(float4*)&C[(size_t)m * ldc + n0 + 4] = o1;
    }
}

// bvec[n] = bp[n] + sum_s bqm[s] * Wp_sample[s, n]
__global__ void bvec_kernel(const float* __restrict__ Wp,
                            const float* __restrict__ bp,
                            const float* __restrict__ bqm)
{
    const int n = blockIdx.x * blockDim.x + threadIdx.x;
    if (n >= EMBED) return;
    float s = bp[n];
    for (int k = 0; k < STOCH; k++)
        s = fmaf(bqm[k], Wp[(size_t)k * EMBED + n], s);
    g_bvec[n] = s;
}

// ---------------------------------------------------------------------------
// Dup+tile passes (layouts verified correct in R11).
// ---------------------------------------------------------------------------
__global__ void dup_gates_kernel(const float* __restrict__ src,
                                 float* __restrict__ dst, int K)
{
    const int nch = K / 32;
    const long total = (long)K * G3;
    for (long o = (long)blockIdx.x * blockDim.x + threadIdx.x; o < total;
         o += (long)gridDim.x * blockDim.x) {
        int jl  = (int)(o & 7);
        long r  = o >> 3;
        int seg = (int)(r % 3);  r /= 3;
        int kk  = (int)(r & 31); r >>= 5;
        int ch  = (int)(r % nch);
        int jblk = (int)(r / nch);
        float v = src[(size_t)(ch * 32 + kk) * G3 + seg * DETER + jblk * 8 + jl];
        *(float2*)&dst[o * 2] = make_float2(v, v);
    }
}

__global__ void dup_proj_kernel(const float* __restrict__ src,
                                float* __restrict__ dst, int K)
{
    const int nch = K / 32;
    const long total = (long)K * EMBED;
    for (long o = (long)blockIdx.x * blockDim.x + threadIdx.x; o < total;
         o += (long)gridDim.x * blockDim.x) {
        int nl  = (int)(o & 3);
        long r  = o >> 2;
        int kk  = (int)(r & 31); r >>= 5;
        int ch  = (int)(r % nch);
        int nblk = (int)(r / nch);
        float v = src[(size_t)(ch * 32 + kk) * EMBED + nblk * 4 + nl];
        *(float2*)&dst[o * 2] = make_float2(v, v);
    }
}

// ---------------------------------------------------------------------------
// Scan GEMM cores. A read directly from gmem (plain cached LDG, 8-deep rolling
// register prefetch). W streamed via properly-pipelined cp.async double buffer
// (wait_group 1 while one prefetch group is in flight).
// sWp: 2 x 1536 floats.
// ---------------------------------------------------------------------------

// 2m x 1n projection accumulate over K = nch*32.
__device__ __forceinline__ u64 proj_accum(
    const float* AT, const float* __restrict__ Wb, int nch,
    float* sWp, int tid, int mb, int nloc2)
{
    const int Ktot = nch * 32;
    u64 abuf[8];
    #pragma unroll
    for (int i = 0; i < 8; i++)
        abuf[i] = *(const u64*)(AT + (size_t)i * 128 + mb);

    if (tid < 64) cp16(sWp + tid * 4, Wb + tid * 4);
    cp_commit();
    if (nch > 1) {
        if (tid < 64) cp16(sWp + 1536 + tid * 4, Wb + 256 + tid * 4);
        cp_commit();
    }

    u64 acc = 0ull;
    for (int ch = 0; ch < nch; ch++) {
        if (ch + 1 < nch) cp_wait1(); else cp_wait0();
        __syncthreads();
        const float* sWc = sWp + (ch & 1) * 1536 + nloc2;
        #pragma unroll
        for (int kk = 0; kk < 32; kk++) {
            u64 a = abuf[kk & 7];
            u64 w = *(const u64*)(sWc + kk * 8);
            ffma2(acc, a, w);
            int pf = ch * 32 + kk + 8;
            pf = pf < Ktot ? pf : Ktot - 1;
            abuf[kk & 7] = *(const u64*)(AT + (size_t)pf * 128 + mb);
        }
        __syncthreads();
        if (ch + 2 < nch) {
            if (tid < 64)
                cp16(sWp + (ch & 1) * 1536 + tid * 4,
                     Wb + (size_t)(ch + 2) * 256 + tid * 4);
            cp_commit();
        }
    }
    return acc;
}

// 4m x 1j x 3seg gates accumulate over K = nch*32.
__device__ __forceinline__ void gates_accum(
    u64* aR, u64* aZ, u64* aN,
    const float* AT, const float* __restrict__ Wb, int nch,
    float* sWp, int tid, int mb2, int jloc2)
{
    const int Ktot = nch * 32;
    ulonglong2 abuf[8];
    #pragma unroll
    for (int i = 0; i < 8; i++)
        abuf[i] = *(const ulonglong2*)(AT + (size_t)i * 128 + mb2);

    cp16(sWp + tid * 4, Wb + tid * 4);
    if (tid < 128) cp16(sWp + (tid + 256) * 4, Wb + (tid + 256) * 4);
    cp_commit();
    if (nch > 1) {
        const float* w1 = Wb + 1536;
        cp16(sWp + 1536 + tid * 4, w1 + tid * 4);
        if (tid < 128) cp16(sWp + 1536 + (tid + 256) * 4, w1 + (tid + 256) * 4);
        cp_commit();
    }

    for (int ch = 0; ch < nch; ch++) {
        if (ch + 1 < nch) cp_wait1(); else cp_wait0();
        __syncthreads();
        const float* sWc = sWp + (ch & 1) * 1536 + jloc2;
        #pragma unroll
        for (int kk = 0; kk < 32; kk++) {
            ulonglong2 a = abuf[kk & 7];
            u64 w0 = *(const u64*)(sWc + kk * 48);
            u64 w1 = *(const u64*)(sWc + kk * 48 + 16);
            u64 w2 = *(const u64*)(sWc + kk * 48 + 32);
            ffma2(aR[0], a.x, w0); ffma2(aR[1], a.y, w0);
            ffma2(aZ[0], a.x, w1); ffma2(aZ[1], a.y, w1);
            ffma2(aN[0], a.x, w2); ffma2(aN[1], a.y, w2);
            int pf = ch * 32 + kk + 8;
            pf = pf < Ktot ? pf : Ktot - 1;
            abuf[kk & 7] = *(const ulonglong2*)(AT + (size_t)pf * 128 + mb2);
        }
        __syncthreads();
        if (ch + 2 < nch) {
            const float* wn = Wb + (size_t)(ch + 2) * 1536;
            float* sWn = sWp + (ch & 1) * 1536;
            cp16(sWn + tid * 4, wn + tid * 4);
            if (tid < 128) cp16(sWn + (tid + 256) * 4, wn + (tid + 256) * 4);
            cp_commit();
        }
    }
}

// ---------------------------------------------------------------------------
// Persistent per-level scan. 3 phases / 3 grid barriers per step.
//   P1: h_T  = relu(qh @ Wcomb + bvec + pre_ctx)     (t=0: relu(bp + pre_ctx))
//   P2: gates + GRU -> detT_new (ping-pong) + dets (std layout / d_out)
//   P3: qh_T = relu(det_new @ Wq_det + bq + pre_obs)
// ---------------------------------------------------------------------------
__global__ __launch_bounds__(256, 1) void level_kernel(
    float* __restrict__ dets, int T,
    const float* __restrict__ pre_ctx, int T1,
    const float* __restrict__ pre_obs,
    const float* __restrict__ bih, const float* __restrict__ bhh,
    const float* __restrict__ bq,  const float* __restrict__ bp)
{
    __shared__ __align__(16) float sW[2 * 1536];

    const int tid  = threadIdx.x;
    const int bid  = blockIdx.x;
    const int rg   = tid >> 5;
    const int lane = tid & 31;
    const size_t ldd = (size_t)T * DETER;

    // P2 coords: lanes = 8 m-lanes x 4 j-lanes; warps = 4 m-groups x 2 j-groups
    const int mb2   = (rg & 3) * 32 + (lane & 7) * 4;   // 4 m per thread
    const int jloc  = (rg >> 2) * 4 + (lane >> 3);      // 0..7
    const int jloc2 = jloc * 2;
    const int j     = bid * 8 + jloc;

    // P1/P3 coords: lanes = 16 m-lanes x 2 n-lanes; warps = 4 m-groups x 2 n-groups
    const int mb    = (rg & 3) * 32 + (lane & 15) * 2;  // 2 m per thread
    const int nloc  = (rg >> 2) * 2 + (lane >> 4);      // 0..3
    const int nloc2 = nloc * 2;
    const int n     = bid * 4 + nloc;

    // loop invariants
    const float br   = bih[j] + bhh[j];
    const float bz   = bih[DETER + j] + bhh[DETER + j];
    const float bin_ = bih[2 * DETER + j];
    const float bhn  = bhh[2 * DETER + j];
    const float bp_n = bp[n];
    const float bv_n = g_bvec[n];
    const float bq_n = bq[n];

    const float* Wih_b = g_Wih_d + (size_t)bid * 16 * 1536;
    const float* Whh_b = g_Whh_d + (size_t)bid * 32 * 1536;
    const float* Wq_b  = g_Wq_d  + (size_t)bid * 32 * 256;
    const float* Wc_b  = g_Wc_d  + (size_t)bid * 16 * 256;

    for (int t = 0; t < T; t++) {
        float* detT_new = g_detT[t & 1];
        const float* detT_old = g_detT[(t & 1) ^ 1];

        // ======================= P1: h_T ===================================
        {
            float pc0 = 0.f, pc1 = 0.f;
            if (pre_ctx) {
                const int tt = t & (T1 - 1);
                pc0 = pre_ctx[((size_t)mb * T1 + tt) * EMBED + n];
                pc1 = pre_ctx[((size_t)(mb + 1) * T1 + tt) * EMBED + n];
            }
            float2 v = make_float2(0.f, 0.f);
            if (t > 0)
                v = unpack2(proj_accum(g_qhT, Wc_b, 16, sW, tid, mb, nloc2));
            const float bb = (t == 0) ? bp_n : bv_n;
            float2 o = make_float2(fmaxf(v.x + bb + pc0, 0.f),
                                   fmaxf(v.y + bb + pc1, 0.f));
            *(float2*)&g_hT[n * 128 + mb] = o;
        }
        grid_sync();

        // ============ P2: gates (gi & gh) + GRU combine ====================
        {
            u64 aR[2] = {0ull, 0ull}, aZ[2] = {0ull, 0ull};
            u64 aNi[2] = {0ull, 0ull}, aNh[2] = {0ull, 0ull};

            float4 dold4 = make_float4(0.f, 0.f, 0.f, 0.f);
            if (t > 0)
                dold4 = *(const float4*)&detT_old[j * 128 + mb2];

            gates_accum(aR, aZ, aNi, g_hT, Wih_b, 16, sW, tid, mb2, jloc2);
            if (t > 0)
                gates_accum(aR, aZ, aNh, detT_old, Whh_b, 32, sW, tid, mb2, jloc2);

            float R[4], Z[4], Ni[4], Nh[4], D[4], dn[4];
            { float2 x = unpack2(aR[0]), y = unpack2(aR[1]);
              R[0]=x.x; R[1]=x.y; R[2]=y.x; R[3]=y.y; }
            { float2 x = unpack2(aZ[0]), y = unpack2(aZ[1]);
              Z[0]=x.x; Z[1]=x.y; Z[2]=y.x; Z[3]=y.y; }
            { float2 x = unpack2(aNi[0]), y = unpack2(aNi[1]);
              Ni[0]=x.x; Ni[1]=x.y; Ni[2]=y.x; Ni[3]=y.y; }
            { float2 x = unpack2(aNh[0]), y = unpack2(aNh[1]);
              Nh[0]=x.x; Nh[1]=x.y; Nh[2]=y.x; Nh[3]=y.y; }
            D[0]=dold4.x; D[1]=dold4.y; D[2]=dold4.z; D[3]=dold4.w;

            #pragma unroll
            for (int i = 0; i < 4; i++) {
                float rr = 1.f / (1.f + expf(-(R[i] + br)));
                float zz = 1.f / (1.f + expf(-(Z[i] + bz)));
                float hnn = (t > 0) ? (Nh[i] + bhn) : bhn;
                float nn = tanhf(Ni[i] + bin_ + rr * hnn);
                dn[i] = (1.f - zz) * nn + zz * D[i];
            }
            *(float4*)&detT_new[j * 128 + mb2] =
                make_float4(dn[0], dn[1], dn[2], dn[3]);
            #pragma unroll
            for (int i = 0; i < 4; i++)
                dets[(size_t)(mb2 + i) * ldd + (size_t)t * DETER + j] = dn[i];
        }
        grid_sync();

        // ======================= P3: qh_T ==================================
        {
            const float po0 = pre_obs[((size_t)mb * T + t) * EMBED + n];
            const float po1 = pre_obs[((size_t)(mb + 1) * T + t) * EMBED + n];
            float2 v = unpack2(proj_accum(detT_new, Wq_b, 32, sW, tid, mb, nloc2));
            float2 o = make_float2(fmaxf(v.x + bq_n + po0, 0.f),
                                   fmaxf(v.y + bq_n + po1, 0.f));
            *(float2*)&g_qhT[n * 128 + mb] = o;
        }
        grid_sync();
    }
}

// ---------------------------------------------------------------------------
// Host driver
// ---------------------------------------------------------------------------
extern "C" void kernel_launch(void* const* d_in, const int* in_sizes, int n_in,
                              void* d_out, int out_size)
{
    (void)in_sizes; (void)n_in; (void)out_size;
    const float* obs_arr[3] = {
        (const float*)d_in[0], (const float*)d_in[1], (const float*)d_in[2] };
    const float* Wp  = (const float*)d_in[3];
    const float* bp  = (const float*)d_in[4];
    const float* Wih = (const float*)d_in[5];
    const float* Whh = (const float*)d_in[6];
    const float* bih = (const float*)d_in[7];
    const float* bhh = (const float*)d_in[8];
    const float* Wq  = (const float*)d_in[9];
    const float* bq  = (const float*)d_in[10];
    const float* Wqm = (const float*)d_in[11];
    const float* bqm = (const float*)d_in[12];

    float *d1_, *d2_, *pc_, *po_, *wc_;
    float *wih_d, *whh_d, *wq_d, *wc_d;
    cudaGetSymbolAddress((void**)&d1_, g_dets1);
    cudaGetSymbolAddress((void**)&d2_, g_dets2);
    cudaGetSymbolAddress((void**)&pc_, g_pre_ctx);
    cudaGetSymbolAddress((void**)&po_, g_pre_obs);
    cudaGetSymbolAddress((void**)&wc_, g_Wcomb);
    cudaGetSymbolAddress((void**)&wih_d, g_Wih_d);
    cudaGetSymbolAddress((void**)&whh_d, g_Whh_d);
    cudaGetSymbolAddress((void**)&wq_d,  g_Wq_d);
    cudaGetSymbolAddress((void**)&wc_d,  g_Wc_d);

    const int Ts[3] = { T0, T0 / 4, T0 / 16 };   // 256, 64, 16
    float* dets[3]  = { (float*)d_out, d1_, d2_ };

    for (int level = LVL - 1; level >= 0; level--) {
        const int T = Ts[level];
        const float* Wp_l  = Wp  + (size_t)level * (STOCH + DETER) * EMBED;
        const float* bp_l  = bp  + (size_t)level * EMBED;
        const float* Wih_l = Wih + (size_t)level * EMBED * G3;
        const float* Whh_l = Whh + (size_t)level * DETER * G3;
        const float* bih_l = bih + (size_t)level * G3;
        const float* bhh_l = bhh + (size_t)level * G3;
        const float* Wq_l  = Wq  + (size_t)level * (DETER + OBS_D) * EMBED;
        const float* bq_l  = bq  + (size_t)level * EMBED;
        const float* Wqm_l = Wqm + (size_t)level * EMBED * STOCH;
        const float* bqm_l = bqm + (size_t)level * STOCH;

        // Wcomb = Wqm @ Wp_sample   (512x512, K=128)
        {
            dim3 g(EMBED / 64, EMBED / 64);
            gemm64_kernel<<<g, 128>>>(Wqm_l, STOCH, Wp_l, EMBED,
                                      wc_, EMBED, STOCH);
        }
        bvec_kernel<<<2, 256>>>(Wp_l, bp_l, bqm_l);

        // dup + tile scan weights into smem-image layout
        dup_gates_kernel<<<2048, 256>>>(Wih_l, wih_d, EMBED);
        dup_gates_kernel<<<2048, 256>>>(Whh_l, whh_d, DETER);
        dup_proj_kernel<<<1024, 256>>>(Wq_l, wq_d, DETER);
        dup_proj_kernel<<<1024, 256>>>(wc_,  wc_d, EMBED);

        const float* pre_ctx = nullptr;
        int T1 = 1;
        if (level < LVL - 1) {
            T1 = Ts[level + 1];
            dim3 g(EMBED / 64, (BSZ * T1) / 64);
            gemm64_kernel<<<g, 128>>>(
                dets[level + 1], DETER,
                Wp_l + (size_t)STOCH * EMBED, EMBED,
                pc_, EMBED, DETER);
            pre_ctx = pc_;
        }

        // pre_obs = obs @ Wq_obs  (K=512)
        {
            dim3 g(EMBED / 64, (BSZ * T) / 64);
            gemm64_kernel<<<g, 128>>>(
                obs_arr[level], OBS_D,
                Wq_l + (size_t)DETER * EMBED, EMBED,
                po_, EMBED, OBS_D);
        }

        level_kernel<<<NB, 256>>>(
            dets[level], T, pre_ctx, T1, po_,
            bih_l, bhh_l, bq_l, bp_l);
    }
}

// round 14
// speedup vs baseline: 1.0255x; 1.0255x over previous
#include <cuda_runtime.h>
#include <cstdint>
#include <cstddef>
#include <math.h>

#define LVL   3
#define BSZ   128
#define T0    256
#define STOCH 128
#define DETER 1024
#define EMBED 512
#define OBS_D 512
#define G3    (3*DETER)   // 3072
#define NB    128          // persistent grid, 1 block/SM, all co-resident

typedef unsigned long long u64;

// ---------------------------------------------------------------------------
// Static device scratch. Transposed activations: X_T[k][m], m contiguous (128).
// ---------------------------------------------------------------------------
__device__ __align__(16) float g_hT [EMBED * BSZ];
__device__ __align__(16) float g_qhT[EMBED * BSZ];
__device__ __align__(16) float g_detT[2][DETER * BSZ];   // ping-pong by t&1
__device__ float g_dets1[BSZ * 64 * DETER];
__device__ float g_dets2[BSZ * 16 * DETER];
__device__ float g_pre_ctx[BSZ * 64 * EMBED];
__device__ float g_pre_obs[BSZ * T0 * EMBED];
__device__ float g_Wcomb[EMBED * EMBED];
__device__ float g_bvec[EMBED];
// Packed gates weights: per (jblk,ch,kk,jl): 8 floats {R,R,Z,Z,N,N,0,0}.
// chunk(jblk,ch) = 32kk x 8jl x 8 = 2048 floats = exact smem image.
__device__ __align__(16) float g_Wih_d[512  * 1024 * 8];   // 16.8 MB
__device__ __align__(16) float g_Whh_d[1024 * 1024 * 8];   // 33.6 MB
// Packed proj weights: per (nblk,ch16,kk,nl): {w,w}. chunk = 16x4x2 = 128 floats.
__device__ __align__(16) float g_Wq_d [1024 * 512 * 2];    // 4.2 MB
__device__ __align__(16) float g_Wc_d [512  * 512 * 2];    // 2.1 MB
__device__ unsigned int g_bar_count;
__device__ unsigned int g_bar_gen;

// ---------------------------------------------------------------------------
// Packed fp32 FMA (bit-exact fp32) + cp.async helpers + named barriers
// ---------------------------------------------------------------------------
__device__ __forceinline__ void ffma2(u64& d, u64 a, u64 b) {
    asm("fma.rn.f32x2 %0, %1, %2, %0;" : "+l"(d) : "l"(a), "l"(b));
}
__device__ __forceinline__ float2 unpack2(u64 v) {
    float lo, hi;
    asm("mov.b64 {%0, %1}, %2;" : "=f"(lo), "=f"(hi) : "l"(v));
    return make_float2(lo, hi);
}
__device__ __forceinline__ void cp16(float* s, const float* g) {
    unsigned a = (unsigned)__cvta_generic_to_shared(s);
    asm volatile("cp.async.cg.shared.global [%0], [%1], 16;" :: "r"(a), "l"(g));
}
__device__ __forceinline__ void cp_commit() { asm volatile("cp.async.commit_group;"); }
__device__ __forceinline__ void cp_wait0()  { asm volatile("cp.async.wait_group 0;"); }
__device__ __forceinline__ void cp_wait1()  { asm volatile("cp.async.wait_group 1;"); }
__device__ __forceinline__ void bar_g(int id) {
    asm volatile("bar.sync %0, 256;" :: "r"(id) : "memory");
}

// ---------------------------------------------------------------------------
// Software grid barrier. NB blocks co-resident.
// ---------------------------------------------------------------------------
__device__ __forceinline__ void grid_sync() {
    __syncthreads();
    if (threadIdx.x == 0) {
        volatile unsigned int* genp = &g_bar_gen;
        unsigned int g = *genp;
        __threadfence();
        unsigned int a = atomicAdd(&g_bar_count, 1u);
        if (a == NB - 1u) {
            atomicExch(&g_bar_count, 0u);
            __threadfence();
            atomicAdd(&g_bar_gen, 1u);
        } else {
            while (*genp == g) { }
        }
        __threadfence();
    }
    __syncthreads();
}

// ---------------------------------------------------------------------------
// Precompute GEMM: C[M,N] = A[M,K] @ W[K,N]   (verified)
// ---------------------------------------------------------------------------
__global__ __launch_bounds__(128) void gemm64_kernel(
    const float* __restrict__ A, int lda,
    const float* __restrict__ W, int ldw,
    float* __restrict__ C, int ldc, int K)
{
    constexpr int BM = 64, BN = 64, BK = 16, TM = 4, TN = 8;
    __shared__ float sA[BK][BM + 4];
    __shared__ float sW[BK][BN];

    const int tid  = threadIdx.x;
    const int tx   = tid & 7;
    const int ty   = tid >> 3;
    const int row0 = blockIdx.y * BM;
    const int col0 = blockIdx.x * BN;

    float acc[TM][TN];
    #pragma unroll
    for (int i = 0; i < TM; i++)
        #pragma unroll
        for (int j = 0; j < TN; j++) acc[i][j] = 0.0f;

    for (int k0 = 0; k0 < K; k0 += BK) {
        #pragma unroll
        for (int p = 0; p < 8; p++) {
            int i  = tid + p * 128;
            int kk = i & 15, r = i >> 4;
            sA[kk][r] = A[(size_t)(row0 + r) * lda + (k0 + kk)];
        }
        #pragma unroll
        for (int p = 0; p < 8; p++) {
            int i  = tid + p * 128;
            int kk = i >> 6, cc = i & 63;
            sW[kk][cc] = W[(size_t)(k0 + kk) * ldw + (col0 + cc)];
        }
        __syncthreads();
        #pragma unroll
        for (int kk = 0; kk < BK; kk++) {
            float4 av = *(const float4*)&sA[kk][ty * TM];
            float4 w0 = *(const float4*)&sW[kk][tx * TN];
            float4 w1 = *(const float4*)&sW[kk][tx * TN + 4];
            float a[TM] = {av.x, av.y, av.z, av.w};
            float w[TN] = {w0.x, w0.y, w0.z, w0.w, w1.x, w1.y, w1.z, w1.w};
            #pragma unroll
            for (int i = 0; i < TM; i++)
                #pragma unroll
                for (int j = 0; j < TN; j++)
                    acc[i][j] = fmaf(a[i], w[j], acc[i][j]);
        }
        __syncthreads();
    }

    #pragma unroll
    for (int i = 0; i < TM; i++) {
        int m  = row0 + ty * TM + i;
        int n0 = col0 + tx * TN;
        float4 o0 = {acc[i][0], acc[i][1], acc[i][2], acc[i][3]};
        float4 o1 = {acc[i][4], acc[i][5], acc[i][6], acc[i][7]};
        *(float4*)&C[(size_t)m * ldc + n0]     = o0;
        *(float4*)&C[(size_t)m * ldc + n0 + 4] = o1;
    }
}

// bvec[n] = bp[n] + sum_s bqm[s] * Wp_sample[s, n]
__global__ void bvec_kernel(const float* __restrict__ Wp,
                            const float* __restrict__ bp,
                            const float* __restrict__ bqm)
{
    const int n = blockIdx.x * blockDim.x + threadIdx.x;
    if (n >= EMBED) return;
    float s = bp[n];
    for (int k = 0; k < STOCH; k++)
        s = fmaf(bqm[k], Wp[(size_t)k * EMBED + n], s);
    g_bvec[n] = s;
}

// ---------------------------------------------------------------------------
// Dup+pack passes.
// ---------------------------------------------------------------------------
__global__ void dup_gates_kernel(const float* __restrict__ src,
                                 float* __restrict__ dst, int K)
{
    const int nch = K / 32;
    const long total = (long)K * 1024 * 4;   // float2 pairs (incl pad)
    for (long o = (long)blockIdx.x * blockDim.x + threadIdx.x; o < total;
         o += (long)gridDim.x * blockDim.x) {
        int p   = (int)(o & 3);
        long r  = o >> 2;
        int jl  = (int)(r & 7);  r >>= 3;
        int kk  = (int)(r & 31); r >>= 5;
        int ch  = (int)(r % nch);
        int jblk = (int)(r / nch);
        float v = (p < 3)
            ? src[(size_t)(ch * 32 + kk) * G3 + p * DETER + jblk * 8 + jl]
            : 0.0f;
        *(float2*)&dst[o * 2] = make_float2(v, v);
    }
}

__global__ void dup_proj_kernel(const float* __restrict__ src,
                                float* __restrict__ dst, int K)
{
    const int nch = K / 16;
    const long total = (long)K * EMBED;      // pairs
    for (long o = (long)blockIdx.x * blockDim.x + threadIdx.x; o < total;
         o += (long)gridDim.x * blockDim.x) {
        int nl  = (int)(o & 3);
        long r  = o >> 2;
        int kk  = (int)(r & 15); r >>= 4;
        int ch  = (int)(r % nch);
        int nblk = (int)(r / nch);
        float v = src[(size_t)(ch * 16 + kk) * EMBED + nblk * 4 + nl];
        *(float2*)&dst[o * 2] = make_float2(v, v);
    }
}

// ---------------------------------------------------------------------------
// Gates pass (P2): all 512 threads. A chunks 32kk x 128m (16KB), W 2048 fl.
// ---------------------------------------------------------------------------
__device__ __forceinline__ void gates_pass(
    u64& aR, u64& aZ, u64& aN,
    const float* __restrict__ AT, const float* __restrict__ Wb, int nch,
    float (*sA)[4096], float (*sW)[2048], int tid, int mb, int jl)
{
    cp16(&sA[0][tid * 4],         AT + tid * 4);
    cp16(&sA[0][(tid + 512) * 4], AT + (tid + 512) * 4);
    cp16(&sW[0][tid * 4],         Wb + tid * 4);
    cp_commit();
    if (nch > 1) {
        cp16(&sA[1][tid * 4],         AT + 4096 + tid * 4);
        cp16(&sA[1][(tid + 512) * 4], AT + 4096 + (tid + 512) * 4);
        cp16(&sW[1][tid * 4],         Wb + 2048 + tid * 4);
        cp_commit();
    }
    for (int ch = 0; ch < nch; ch++) {
        if (ch + 1 < nch) cp_wait1(); else cp_wait0();
        __syncthreads();
        const float* sAc = sA[ch & 1];
        const float* sWc = sW[ch & 1];
        #pragma unroll
        for (int kk = 0; kk < 32; kk++) {
            u64 a = *(const u64*)(sAc + kk * 128 + mb);
            const float* wp = sWc + (kk * 8 + jl) * 8;
            ulonglong2 wRZ = *(const ulonglong2*)wp;   // {R,R},{Z,Z}
            u64 wN = *(const u64*)(wp + 4);            // {N,N}
            ffma2(aR, a, wRZ.x);
            ffma2(aZ, a, wRZ.y);
            ffma2(aN, a, wN);
        }
        __syncthreads();
        if (ch + 2 < nch) {
            const int b = ch & 1;
            const float* an = AT + (size_t)(ch + 2) * 4096;
            cp16(&sA[b][tid * 4],         an + tid * 4);
            cp16(&sA[b][(tid + 512) * 4], an + (tid + 512) * 4);
            cp16(&sW[b][tid * 4],         Wb + (size_t)(ch + 2) * 2048 + tid * 4);
            cp_commit();
        }
    }
}

// ---------------------------------------------------------------------------
// Projection pass (P1/P3): group-local (256 threads, named barrier gbar).
// Chunk = 16kk x 128m A (2048 floats: 2 cp16/thread) + 128 floats W
// (32 cp16 from lt<32). FIXED from R13: full-chunk staging.
// ---------------------------------------------------------------------------
__device__ __forceinline__ u64 proj_pass(
    const float* __restrict__ AT, const float* __restrict__ Wb,
    int ch0, int nchg,
    float* Ab, float* Wbuf, int lt, int mb, int nl, int gbar)
{
    u64 acc = 0ull;
    {
        const float* a0 = AT + (size_t)ch0 * 2048;
        cp16(Ab + lt * 4,         a0 + lt * 4);
        cp16(Ab + (lt + 256) * 4, a0 + (lt + 256) * 4);
        if (lt < 32) cp16(Wbuf + lt * 4, Wb + (size_t)ch0 * 128 + lt * 4);
        cp_commit();
    }
    {
        const float* a1 = AT + (size_t)(ch0 + 1) * 2048;
        cp16(Ab + 2048 + lt * 4,         a1 + lt * 4);
        cp16(Ab + 2048 + (lt + 256) * 4, a1 + (lt + 256) * 4);
        if (lt < 32) cp16(Wbuf + 128 + lt * 4, Wb + (size_t)(ch0 + 1) * 128 + lt * 4);
        cp_commit();
    }

    for (int i = 0; i < nchg; i++) {
        if (i + 1 < nchg) cp_wait1(); else cp_wait0();
        bar_g(gbar);
        const float* sAc = Ab + (i & 1) * 2048;
        const float* sWc = Wbuf + (i & 1) * 128;
        #pragma unroll
        for (int kk = 0; kk < 16; kk++) {
            u64 a = *(const u64*)(sAc + kk * 128 + mb);
            u64 w = *(const u64*)(sWc + (kk * 4 + nl) * 2);
            ffma2(acc, a, w);
        }
        bar_g(gbar);
        if (i + 2 < nchg) {
            const int b = i & 1;
            const float* an = AT + (size_t)(ch0 + i + 2) * 2048;
            cp16(Ab + b * 2048 + lt * 4,         an + lt * 4);
            cp16(Ab + b * 2048 + (lt + 256) * 4, an + (lt + 256) * 4);
            if (lt < 32)
                cp16(Wbuf + b * 128 + lt * 4,
                     Wb + (size_t)(ch0 + i + 2) * 128 + lt * 4);
            cp_commit();
        }
    }
    return acc;
}

// ---------------------------------------------------------------------------
// Persistent per-level scan. 128 blocks x 512 threads. 3 phases / step.
// ---------------------------------------------------------------------------
__global__ __launch_bounds__(512, 1) void level_kernel(
    float* __restrict__ dets, int T,
    const float* __restrict__ pre_ctx, int T1,
    const float* __restrict__ pre_obs,
    const float* __restrict__ bih, const float* __restrict__ bhh,
    const float* __restrict__ bq,  const float* __restrict__ bp)
{
    __shared__ __align__(16) float sA[2][4096];   // 32 KB
    __shared__ __align__(16) float sW[2][2048];   // 16 KB

    const int tid  = threadIdx.x;
    const int bid  = blockIdx.x;
    const int rg   = tid >> 5;
    const int lane = tid & 31;
    const size_t ldd = (size_t)T * DETER;

    // P2: thread tile 2m x 1j. 8 m-warpgroups x 2 j-warpgroups.
    const int mb = (rg & 7) * 16 + (lane & 7) * 2;   // even, 0..126
    const int jl = (rg >> 3) * 4 + (lane >> 3);      // 0..7
    const int j  = bid * 8 + jl;

    // P1/P3: two 256-thread K-split groups; thread tile 2m x 1n.
    const int g    = rg >> 3;           // 0 or 1
    const int lt   = tid & 255;
    const int nl   = lane >> 3;         // 0..3
    const int n    = bid * 4 + nl;
    const int gbar = g + 1;

    float* AbG   = sA[g];               // group A double buffer (2 x 2048)
    float* WbufG = &sW[0][g * 256];     // group W double buffer (2 x 128)
    u64*   Red   = (u64*)&sW[1][0];     // 256 u64 reduction slots

    const float br   = bih[j] + bhh[j];
    const float bz   = bih[DETER + j] + bhh[DETER + j];
    const float bin_ = bih[2 * DETER + j];
    const float bhn  = bhh[2 * DETER + j];
    const float bp_n = bp[n];
    const float bv_n = g_bvec[n];
    const float bq_n = bq[n];

    const float* Wih_b = g_Wih_d + (size_t)bid * 16 * 2048;
    const float* Whh_b = g_Whh_d + (size_t)bid * 32 * 2048;
    const float* Wq_b  = g_Wq_d  + (size_t)bid * 64 * 128;
    const float* Wc_b  = g_Wc_d  + (size_t)bid * 32 * 128;

    const int slot = (mb >> 1) * 4 + nl;   // 0..255

    for (int t = 0; t < T; t++) {
        float* detT_new = g_detT[t & 1];
        const float* detT_old = g_detT[(t & 1) ^ 1];

        // ======================= P1: h_T ===================================
        {
            float pc0 = 0.f, pc1 = 0.f;
            if (pre_ctx) {
                const int tt = t & (T1 - 1);
                pc0 = pre_ctx[((size_t)mb * T1 + tt) * EMBED + n];
                pc1 = pre_ctx[((size_t)(mb + 1) * T1 + tt) * EMBED + n];
            }
            u64 acc = 0ull;
            if (t > 0)
                acc = proj_pass(g_qhT, Wc_b, g * 16, 16,
                                AbG, WbufG, lt, mb, nl, gbar);
            if (g == 1) Red[slot] = acc;
            __syncthreads();
            if (g == 0) {
                float2 v = unpack2(acc);
                float2 r = unpack2(Red[slot]);
                const float bb = (t == 0) ? bp_n : bv_n;
                float o0 = fmaxf(v.x + r.x + bb + pc0, 0.f);
                float o1 = fmaxf(v.y + r.y + bb + pc1, 0.f);
                *(float2*)&g_hT[n * 128 + mb] = make_float2(o0, o1);
            }
        }
        grid_sync();

        // ============ P2: gates (gi & gh) + GRU combine ====================
        {
            u64 aR = 0ull, aZ = 0ull, aNi = 0ull, aNh = 0ull;
            float2 dold = make_float2(0.f, 0.f);
            if (t > 0)
                dold = *(const float2*)&detT_old[j * 128 + mb];

            gates_pass(aR, aZ, aNi, g_hT, Wih_b, 16, sA, sW, tid, mb, jl);
            if (t > 0)
                gates_pass(aR, aZ, aNh, detT_old, Whh_b, 32, sA, sW, tid, mb, jl);

            float2 R = unpack2(aR), Z = unpack2(aZ);
            float2 Ni = unpack2(aNi), Nh = unpack2(aNh);
            float dn0, dn1;
            {
                float rr = 1.f / (1.f + expf(-(R.x + br)));
                float zz = 1.f / (1.f + expf(-(Z.x + bz)));
                float nn = tanhf(Ni.x + bin_ + rr * (Nh.x + bhn));
                dn0 = (1.f - zz) * nn + zz * dold.x;
            }
            {
                float rr = 1.f / (1.f + expf(-(R.y + br)));
                float zz = 1.f / (1.f + expf(-(Z.y + bz)));
                float nn = tanhf(Ni.y + bin_ + rr * (Nh.y + bhn));
                dn1 = (1.f - zz) * nn + zz * dold.y;
            }
            *(float2*)&detT_new[j * 128 + mb] = make_float2(dn0, dn1);
            dets[(size_t)mb * ldd + (size_t)t * DETER + j]       = dn0;
            dets[(size_t)(mb + 1) * ldd + (size_t)t * DETER + j] = dn1;
        }
        grid_sync();

        // ======================= P3: qh_T ==================================
        {
            const float po0 = pre_obs[((size_t)mb * T + t) * EMBED + n];
            const float po1 = pre_obs[((size_t)(mb + 1) * T + t) * EMBED + n];
            u64 acc = proj_pass(detT_new, Wq_b, g * 32, 32,
                                AbG, WbufG, lt, mb, nl, gbar);
            if (g == 1) Red[slot] = acc;
            __syncthreads();
            if (g == 0) {
                float2 v = unpack2(acc);
                float2 r = unpack2(Red[slot]);
                float o0 = fmaxf(v.x + r.x + bq_n + po0, 0.f);
                float o1 = fmaxf(v.y + r.y + bq_n + po1, 0.f);
                *(float2*)&g_qhT[n * 128 + mb] = make_float2(o0, o1);
            }
        }
        grid_sync();
    }
}

// ---------------------------------------------------------------------------
// Host driver
// ---------------------------------------------------------------------------
extern "C" void kernel_launch(void* const* d_in, const int* in_sizes, int n_in,
                              void* d_out, int out_size)
{
    (void)in_sizes; (void)n_in; (void)out_size;
    const float* obs_arr[3] = {
        (const float*)d_in[0], (const float*)d_in[1], (const float*)d_in[2] };
    const float* Wp  = (const float*)d_in[3];
    const float* bp  = (const float*)d_in[4];
    const float* Wih = (const float*)d_in[5];
    const float* Whh = (const float*)d_in[6];
    const float* bih = (const float*)d_in[7];
    const float* bhh = (const float*)d_in[8];
    const float* Wq  = (const float*)d_in[9];
    const float* bq  = (const float*)d_in[10];
    const float* Wqm = (const float*)d_in[11];
    const float* bqm = (const float*)d_in[12];

    float *d1_, *d2_, *pc_, *po_, *wc_;
    float *wih_d, *whh_d, *wq_d, *wc_d;
    cudaGetSymbolAddress((void**)&d1_, g_dets1);
    cudaGetSymbolAddress((void**)&d2_, g_dets2);
    cudaGetSymbolAddress((void**)&pc_, g_pre_ctx);
    cudaGetSymbolAddress((void**)&po_, g_pre_obs);
    cudaGetSymbolAddress((void**)&wc_, g_Wcomb);
    cudaGetSymbolAddress((void**)&wih_d, g_Wih_d);
    cudaGetSymbolAddress((void**)&whh_d, g_Whh_d);
    cudaGetSymbolAddress((void**)&wq_d,  g_Wq_d);
    cudaGetSymbolAddress((void**)&wc_d,  g_Wc_d);

    const int Ts[3] = { T0, T0 / 4, T0 / 16 };   // 256, 64, 16
    float* dets[3]  = { (float*)d_out, d1_, d2_ };

    for (int level = LVL - 1; level >= 0; level--) {
        const int T = Ts[level];
        const float* Wp_l  = Wp  + (size_t)level * (STOCH + DETER) * EMBED;
        const float* bp_l  = bp  + (size_t)level * EMBED;
        const float* Wih_l = Wih + (size_t)level * EMBED * G3;
        const float* Whh_l = Whh + (size_t)level * DETER * G3;
        const float* bih_l = bih + (size_t)level * G3;
        const float* bhh_l = bhh + (size_t)level * G3;
        const float* Wq_l  = Wq  + (size_t)level * (DETER + OBS_D) * EMBED;
        const float* bq_l  = bq  + (size_t)level * EMBED;
        const float* Wqm_l = Wqm + (size_t)level * EMBED * STOCH;
        const float* bqm_l = bqm + (size_t)level * STOCH;

        // Wcomb = Wqm @ Wp_sample   (512x512, K=128)
        {
            dim3 gr(EMBED / 64, EMBED / 64);
            gemm64_kernel<<<gr, 128>>>(Wqm_l, STOCH, Wp_l, EMBED,
                                       wc_, EMBED, STOCH);
        }
        bvec_kernel<<<2, 256>>>(Wp_l, bp_l, bqm_l);

        // pack scan weights into smem-image layouts
        dup_gates_kernel<<<2048, 256>>>(Wih_l, wih_d, EMBED);
        dup_gates_kernel<<<2048, 256>>>(Whh_l, whh_d, DETER);
        dup_proj_kernel<<<1024, 256>>>(Wq_l, wq_d, DETER);
        dup_proj_kernel<<<1024, 256>>>(wc_,  wc_d, EMBED);

        const float* pre_ctx = nullptr;
        int T1 = 1;
        if (level < LVL - 1) {
            T1 = Ts[level + 1];
            dim3 gr(EMBED / 64, (BSZ * T1) / 64);
            gemm64_kernel<<<gr, 128>>>(
                dets[level + 1], DETER,
                Wp_l + (size_t)STOCH * EMBED, EMBED,
                pc_, EMBED, DETER);
            pre_ctx = pc_;
        }

        // pre_obs = obs @ Wq_obs  (K=512)
        {
            dim3 gr(EMBED / 64, (BSZ * T) / 64);
            gemm64_kernel<<<gr, 128>>>(
                obs_arr[level], OBS_D,
                Wq_l + (size_t)DETER * EMBED, EMBED,
                po_, EMBED, OBS_D);
        }

        level_kernel<<<NB, 512>>>(
            dets[level], T, pre_ctx, T1, po_,
            bih_l, bhh_l, bq_l, bp_l);
    }
}

// round 15
// speedup vs baseline: 1.0827x; 1.0558x over previous
#include <cuda_runtime.h>
#include <cstdint>
#include <cstddef>
#include <math.h>

#define LVL   3
#define BSZ   128
#define T0    256
#define STOCH 128
#define DETER 1024
#define EMBED 512
#define OBS_D 512
#define G3    (3*DETER)   // 3072
#define NB    128          // persistent grid, 1 block/SM, all co-resident

typedef unsigned long long u64;
typedef unsigned int u32;

// ---------------------------------------------------------------------------
// Static device scratch. Transposed activations: X_T[k][m], m contiguous (128).
// ---------------------------------------------------------------------------
__device__ __align__(16) float g_hT [EMBED * BSZ];
__device__ __align__(16) float g_qhT[EMBED * BSZ];
__device__ __align__(16) float g_detT[2][DETER * BSZ];   // ping-pong by t&1
__device__ float g_dets1[BSZ * 64 * DETER];
__device__ float g_dets2[BSZ * 16 * DETER];
__device__ float g_pre_ctx[BSZ * 64 * EMBED];
__device__ float g_pre_obs[BSZ * T0 * EMBED];
__device__ float g_Wcomb[EMBED * EMBED];
__device__ float g_bvec[LVL][EMBED];
// Packed gates weights (per level): per (jblk,ch,kk,jl): {R,R,Z,Z,N,N,0,0}.
// chunk(jblk,ch) = 32kk x 8jl x 8 = 2048 floats = exact smem image.
__device__ __align__(16) float g_Wih_d[LVL][512  * 1024 * 8];   // 3 x 16.8 MB
__device__ __align__(16) float g_Whh_d[LVL][1024 * 1024 * 8];   // 3 x 33.6 MB
// Packed proj weights: per (nblk,ch32,kk,nl): {w,w}. chunk = 32x4x2 = 256 fl.
__device__ __align__(16) float g_Wq_d [LVL][1024 * 512 * 2];    // 3 x 4.2 MB
__device__ __align__(16) float g_Wc_d [512 * 512 * 2];          // 2.1 MB
__device__ unsigned int g_bar_count;
__device__ unsigned int g_bar_gen;

// ---------------------------------------------------------------------------
// Packed fp32 FMA (bit-exact fp32) + bulk-copy / mbarrier helpers
// ---------------------------------------------------------------------------
__device__ __forceinline__ void ffma2(u64& d, u64 a, u64 b) {
    asm("fma.rn.f32x2 %0, %1, %2, %0;" : "+l"(d) : "l"(a), "l"(b));
}
__device__ __forceinline__ float2 unpack2(u64 v) {
    float lo, hi;
    asm("mov.b64 {%0, %1}, %2;" : "=f"(lo), "=f"(hi) : "l"(v));
    return make_float2(lo, hi);
}
__device__ __forceinline__ void bulkcp(u32 dst, const float* src, u32 bytes, u32 mbar) {
    asm volatile(
        "cp.async.bulk.shared::cluster.global.mbarrier::complete_tx::bytes "
        "[%0], [%1], %2, [%3];"
        :: "r"(dst), "l"(src), "r"(bytes), "r"(mbar) : "memory");
}
__device__ __forceinline__ void mb_init(u32 mbar, u32 cnt) {
    asm volatile("mbarrier.init.shared.b64 [%0], %1;" :: "r"(mbar), "r"(cnt) : "memory");
}
__device__ __forceinline__ void mb_expect(u32 mbar, u32 bytes) {
    asm volatile("mbarrier.arrive.expect_tx.shared.b64 _, [%0], %1;"
                 :: "r"(mbar), "r"(bytes) : "memory");
}
__device__ __forceinline__ void mwait(u32 mbar, u32 parity) {
    u32 done;
    asm volatile(
        "{\n\t.reg .pred p;\n\t"
        "mbarrier.try_wait.parity.acquire.cta.shared::cta.b64 p, [%1], %2;\n\t"
        "selp.b32 %0, 1, 0, p;\n\t}"
        : "=r"(done) : "r"(mbar), "r"(parity) : "memory");
    if (!done) {
        asm volatile(
            "{\n\t.reg .pred P1;\n\t"
            "WAIT_LOOP_%=:\n\t"
            "mbarrier.try_wait.parity.acquire.cta.shared::cta.b64 P1, [%0], %1, 0x989680;\n\t"
            "@P1 bra.uni WAIT_DONE_%=;\n\t"
            "bra.uni WAIT_LOOP_%=;\n\t"
            "WAIT_DONE_%=:\n\t}"
            :: "r"(mbar), "r"(parity) : "memory");
    }
}
__device__ __forceinline__ void bar_g(int id) {
    asm volatile("bar.sync %0, 256;" :: "r"(id) : "memory");
}

// ---------------------------------------------------------------------------
// Software grid barrier. NB blocks co-resident. fence.proxy.async at exit
// orders the just-acquired generic writes against later bulk-copy reads.
// ---------------------------------------------------------------------------
__device__ __forceinline__ void grid_sync() {
    __syncthreads();
    if (threadIdx.x == 0) {
        volatile unsigned int* genp = &g_bar_gen;
        unsigned int g = *genp;
        __threadfence();
        unsigned int a = atomicAdd(&g_bar_count, 1u);
        if (a == NB - 1u) {
            atomicExch(&g_bar_count, 0u);
            __threadfence();
            atomicAdd(&g_bar_gen, 1u);
        } else {
            while (*genp == g) { }
        }
        __threadfence();
    }
    __syncthreads();
    if ((threadIdx.x & 255) == 0)
        asm volatile("fence.proxy.async;" ::: "memory");
}

// ---------------------------------------------------------------------------
// Precompute GEMM: C[M,N] = A[M,K] @ W[K,N]   (verified)
// ---------------------------------------------------------------------------
__global__ __launch_bounds__(128) void gemm64_kernel(
    const float* __restrict__ A, int lda,
    const float* __restrict__ W, int ldw,
    float* __restrict__ C, int ldc, int K)
{
    constexpr int BM = 64, BN = 64, BK = 16, TM = 4, TN = 8;
    __shared__ float sA[BK][BM + 4];
    __shared__ float sW[BK][BN];

    const int tid  = threadIdx.x;
    const int tx   = tid & 7;
    const int ty   = tid >> 3;
    const int row0 = blockIdx.y * BM;
    const int col0 = blockIdx.x * BN;

    float acc[TM][TN];
    #pragma unroll
    for (int i = 0; i < TM; i++)
        #pragma unroll
        for (int j = 0; j < TN; j++) acc[i][j] = 0.0f;

    for (int k0 = 0; k0 < K; k0 += BK) {
        #pragma unroll
        for (int p = 0; p < 8; p++) {
            int i  = tid + p * 128;
            int kk = i & 15, r = i >> 4;
            sA[kk][r] = A[(size_t)(row0 + r) * lda + (k0 + kk)];
        }
        #pragma unroll
        for (int p = 0; p < 8; p++) {
            int i  = tid + p * 128;
            int kk = i >> 6, cc = i & 63;
            sW[kk][cc] = W[(size_t)(k0 + kk) * ldw + (col0 + cc)];
        }
        __syncthreads();
        #pragma unroll
        for (int kk = 0; kk < BK; kk++) {
            float4 av = *(const float4*)&sA[kk][ty * TM];
            float4 w0 = *(const float4*)&sW[kk][tx * TN];
            float4 w1 = *(const float4*)&sW[kk][tx * TN + 4];
            float a[TM] = {av.x, av.y, av.z, av.w};
            float w[TN] = {w0.x, w0.y, w0.z, w0.w, w1.x, w1.y, w1.z, w1.w};
            #pragma unroll
            for (int i = 0; i < TM; i++)
                #pragma unroll
                for (int j = 0; j < TN; j++)
                    acc[i][j] = fmaf(a[i], w[j], acc[i][j]);
        }
        __syncthreads();
    }

    #pragma unroll
    for (int i = 0; i < TM; i++) {
        int m  = row0 + ty * TM + i;
        int n0 = col0 + tx * TN;
        float4 o0 = {acc[i][0], acc[i][1], acc[i][2], acc[i][3]};
        float4 o1 = {acc[i][4], acc[i][5], acc[i][6], acc[i][7]};
        *(float4*)&C[(size_t)m * ldc + n0]     = o0;
        *(float4*)&C[(size_t)m * ldc + n0 + 4] = o1;
    }
}

// bvec[lvl][n] = bp[n] + sum_s bqm[s] * Wp_sample[s, n]
__global__ void bvec_kernel(const float* __restrict__ Wp,
                            const float* __restrict__ bp,
                            const float* __restrict__ bqm, int lvl)
{
    const int n = blockIdx.x * blockDim.x + threadIdx.x;
    if (n >= EMBED) return;
    float s = bp[n];
    for (int k = 0; k < STOCH; k++)
        s = fmaf(bqm[k], Wp[(size_t)k * EMBED + n], s);
    g_bvec[lvl][n] = s;
}

// ---------------------------------------------------------------------------
// Fused pack kernel: all levels' Wih/Whh (gates layout) + Wq (proj layout).
// ---------------------------------------------------------------------------
__device__ __forceinline__ void pack_gates(const float* src, float* dst,
                                           int K, long base, long stride)
{
    const int nch = K / 32;
    const long total = (long)K * 1024 * 4;   // pairs incl pad
    for (long o = base; o < total; o += stride) {
        int p   = (int)(o & 3);
        long r  = o >> 2;
        int jl  = (int)(r & 7);  r >>= 3;
        int kk  = (int)(r & 31); r >>= 5;
        int ch  = (int)(r % nch);
        int jblk = (int)(r / nch);
        float v = (p < 3)
            ? src[(size_t)(ch * 32 + kk) * G3 + p * DETER + jblk * 8 + jl]
            : 0.0f;
        *(float2*)&dst[o * 2] = make_float2(v, v);
    }
}

__device__ __forceinline__ void pack_proj(const float* src, float* dst,
                                          int K, long base, long stride)
{
    const int nch = K / 32;
    const long total = (long)K * EMBED;      // pairs
    for (long o = base; o < total; o += stride) {
        int nl  = (int)(o & 3);
        long r  = o >> 2;
        int kk  = (int)(r & 31); r >>= 5;
        int ch  = (int)(r % nch);
        int nblk = (int)(r / nch);
        float v = src[(size_t)(ch * 32 + kk) * EMBED + nblk * 4 + nl];
        *(float2*)&dst[o * 2] = make_float2(v, v);
    }
}

__global__ void pack_all_kernel(const float* __restrict__ Wih,
                                const float* __restrict__ Whh,
                                const float* __restrict__ Wq)
{
    const long base   = (long)blockIdx.x * blockDim.x + threadIdx.x;
    const long stride = (long)gridDim.x * blockDim.x;
    for (int l = 0; l < LVL; l++) {
        pack_gates(Wih + (size_t)l * EMBED * G3, g_Wih_d[l], EMBED, base, stride);
        pack_gates(Whh + (size_t)l * DETER * G3, g_Whh_d[l], DETER, base, stride);
        pack_proj (Wq  + (size_t)l * (DETER + OBS_D) * EMBED, g_Wq_d[l], DETER,
                   base, stride);
    }
}

// proj pack for Wcomb (per level, after its gemm)
__global__ void pack_wc_kernel(const float* __restrict__ src)
{
    const long base   = (long)blockIdx.x * blockDim.x + threadIdx.x;
    const long stride = (long)gridDim.x * blockDim.x;
    pack_proj(src, g_Wc_d, EMBED, base, stride);
}

// ---------------------------------------------------------------------------
// Dynamic smem layout (float indices):
//   A bufs:   4 x 4096   @ 0      (gates uses 0,1; proj g0 -> 0,1; g1 -> 2,3)
//   gates W:  2 x 2048   @ 16384
//   proj W:   4 x 256    @ 20480  (g0 b0,b1; g1 b0,b1)
//   Red:      512        @ 21504  (256 u64)
//   mbarriers (bytes 88064+): 0,1 gates; 2,3 proj g0; 4,5 proj g1
// ---------------------------------------------------------------------------
#define SM_A(k)     ((k) * 4096)
#define SM_GW(b)    (16384 + (b) * 2048)
#define SM_PW(g,b)  (20480 + ((g) * 2 + (b)) * 256)
#define SM_RED      21504
#define MB_OFF      88064
#define SMEM_BYTES  (88064 + 64)

// ---------------------------------------------------------------------------
// Gates pass (P2): all 512 threads. A chunk 16KB, W chunk 8KB, bulk-copied.
// ---------------------------------------------------------------------------
__device__ __forceinline__ void gates_pass(
    u64& aR, u64& aZ, u64& aN,
    const float* __restrict__ AT, const float* __restrict__ Wb, int nch,
    float* smem, u32 sb, u32& ph0, u32& ph1,
    int tid, int mb, int jl)
{
    const u32 m0 = sb + MB_OFF, m1 = m0 + 8;
    if (tid == 0) {
        mb_expect(m0, 24576);
        bulkcp(sb + SM_A(0) * 4,  AT, 16384, m0);
        bulkcp(sb + SM_GW(0) * 4, Wb, 8192,  m0);
        mb_expect(m1, 24576);
        bulkcp(sb + SM_A(1) * 4,  AT + 4096, 16384, m1);
        bulkcp(sb + SM_GW(1) * 4, Wb + 2048, 8192,  m1);
    }
    for (int ch = 0; ch < nch; ch++) {
        const int b = ch & 1;
        mwait(b ? m1 : m0, b ? ph1 : ph0);
        if (b) ph1 ^= 1u; else ph0 ^= 1u;
        const float* sAc = smem + SM_A(b);
        const float* sWc = smem + SM_GW(b);
        #pragma unroll
        for (int kk = 0; kk < 32; kk++) {
            u64 a = *(const u64*)(sAc + kk * 128 + mb);
            const float* wp = sWc + (kk * 8 + jl) * 8;
            ulonglong2 wRZ = *(const ulonglong2*)wp;   // {R,R},{Z,Z}
            u64 wN = *(const u64*)(wp + 4);            // {N,N}
            ffma2(aR, a, wRZ.x);
            ffma2(aZ, a, wRZ.y);
            ffma2(aN, a, wN);
        }
        __syncthreads();
        if (ch + 2 < nch && tid == 0) {
            const u32 m = b ? m1 : m0;
            mb_expect(m, 24576);
            bulkcp(sb + SM_A(b) * 4,  AT + (size_t)(ch + 2) * 4096, 16384, m);
            bulkcp(sb + SM_GW(b) * 4, Wb + (size_t)(ch + 2) * 2048, 8192,  m);
        }
    }
    __syncthreads();
}

// ---------------------------------------------------------------------------
// Projection pass (P1/P3): group-local (256 threads). A chunk 16KB (32kk),
// W chunk 1KB, bulk-copied on group mbarriers.
// ---------------------------------------------------------------------------
__device__ __forceinline__ u64 proj_pass(
    const float* __restrict__ AT, const float* __restrict__ Wb, int nchg,
    float* smem, u32 sb, int abase, int wbase, int mbidx,
    u32& ph0, u32& ph1, int lt, int mb, int nl, int gbar)
{
    const u32 mA = sb + MB_OFF + mbidx * 8, mB = mA + 8;
    if (lt == 0) {
        mb_expect(mA, 17408);
        bulkcp(sb + abase * 4, AT, 16384, mA);
        bulkcp(sb + wbase * 4, Wb, 1024,  mA);
        mb_expect(mB, 17408);
        bulkcp(sb + (abase + 4096) * 4, AT + 4096, 16384, mB);
        bulkcp(sb + (wbase + 256) * 4,  Wb + 256,  1024,  mB);
    }
    u64 acc = 0ull;
    for (int i = 0; i < nchg; i++) {
        const int b = i & 1;
        mwait(b ? mB : mA, b ? ph1 : ph0);
        if (b) ph1 ^= 1u; else ph0 ^= 1u;
        const float* sAc = smem + abase + b * 4096;
        const float* sWc = smem + wbase + b * 256;
        #pragma unroll
        for (int kk = 0; kk < 32; kk++) {
            u64 a = *(const u64*)(sAc + kk * 128 + mb);
            u64 w = *(const u64*)(sWc + (kk * 4 + nl) * 2);
            ffma2(acc, a, w);
        }
        bar_g(gbar);
        if (i + 2 < nchg && lt == 0) {
            const u32 m = b ? mB : mA;
            mb_expect(m, 17408);
            bulkcp(sb + (abase + b * 4096) * 4, AT + (size_t)(i + 2) * 4096, 16384, m);
            bulkcp(sb + (wbase + b * 256) * 4,  Wb + (size_t)(i + 2) * 256,  1024,  m);
        }
    }
    bar_g(gbar);
    return acc;
}

// ---------------------------------------------------------------------------
// Persistent per-level scan. 128 blocks x 512 threads. 3 phases / step.
// ---------------------------------------------------------------------------
__global__ __launch_bounds__(512, 1) void level_kernel(
    float* __restrict__ dets, int T,
    const float* __restrict__ pre_ctx, int T1,
    const float* __restrict__ pre_obs,
    const float* __restrict__ Wih_p, const float* __restrict__ Whh_p,
    const float* __restrict__ Wq_p,
    const float* __restrict__ bih, const float* __restrict__ bhh,
    const float* __restrict__ bq,  const float* __restrict__ bp, int lvl)
{
    extern __shared__ __align__(16) float smem[];
    const u32 sb = (u32)__cvta_generic_to_shared(smem);

    const int tid  = threadIdx.x;
    const int bid  = blockIdx.x;
    const int rg   = tid >> 5;
    const int lane = tid & 31;
    const size_t ldd = (size_t)T * DETER;

    if (tid == 0) {
        #pragma unroll
        for (int k = 0; k < 6; k++) mb_init(sb + MB_OFF + k * 8, 1);
    }
    __syncthreads();

    // P2 coords (R14-verified): thread tile 2m x 1j.
    const int mb = (rg & 7) * 16 + (lane & 7) * 2;   // even, 0..126
    const int jl = (rg >> 3) * 4 + (lane >> 3);      // 0..7
    const int j  = bid * 8 + jl;

    // P1/P3 coords (R14-verified): two 256-thread K-split groups.
    const int g    = rg >> 3;           // 0 or 1
    const int lt   = tid & 255;
    const int nl   = lane >> 3;         // 0..3
    const int n    = bid * 4 + nl;
    const int gbar = g + 1;
    const int abase = g * 8192;         // A bufs: g0 -> 0,1 ; g1 -> 2,3
    const int wbase = SM_PW(g, 0);
    const int mbidx = 2 + g * 2;

    u64* Red = (u64*)(smem + SM_RED);
    const int slot = (mb >> 1) * 4 + nl;   // 0..255

    const float br   = bih[j] + bhh[j];
    const float bz   = bih[DETER + j] + bhh[DETER + j];
    const float bin_ = bih[2 * DETER + j];
    const float bhn  = bhh[2 * DETER + j];
    const float bp_n = bp[n];
    const float bv_n = g_bvec[lvl][n];
    const float bq_n = bq[n];

    const float* Wih_b = Wih_p + (size_t)bid * 16 * 2048;
    const float* Whh_b = Whh_p + (size_t)bid * 32 * 2048;
    const float* Wq_b  = Wq_p  + (size_t)bid * 32 * 256;
    const float* Wc_b  = g_Wc_d + (size_t)bid * 16 * 256;

    u32 phG0 = 0, phG1 = 0;   // gates barrier phases
    u32 phP0 = 0, phP1 = 0;   // this group's proj barrier phases

    for (int t = 0; t < T; t++) {
        float* detT_new = g_detT[t & 1];
        const float* detT_old = g_detT[(t & 1) ^ 1];

        // ======================= P1: h_T ===================================
        {
            float pc0 = 0.f, pc1 = 0.f;
            if (pre_ctx) {
                const int tt = t & (T1 - 1);
                pc0 = pre_ctx[((size_t)mb * T1 + tt) * EMBED + n];
                pc1 = pre_ctx[((size_t)(mb + 1) * T1 + tt) * EMBED + n];
            }
            u64 acc = 0ull;
            if (t > 0)
                acc = proj_pass(g_qhT + g * 32768, Wc_b + g * 2048, 8,
                                smem, sb, abase, wbase, mbidx,
                                phP0, phP1, lt, mb, nl, gbar);
            if (g == 1) Red[slot] = acc;
            __syncthreads();
            if (g == 0) {
                float2 v = unpack2(acc);
                float2 r = unpack2(Red[slot]);
                const float bb = (t == 0) ? bp_n : bv_n;
                float o0 = fmaxf(v.x + r.x + bb + pc0, 0.f);
                float o1 = fmaxf(v.y + r.y + bb + pc1, 0.f);
                *(float2*)&g_hT[n * 128 + mb] = make_float2(o0, o1);
            }
        }
        grid_sync();

        // ============ P2: gates (gi & gh) + GRU combine ====================
        {
            u64 aR = 0ull, aZ = 0ull, aNi = 0ull, aNh = 0ull;
            float2 dold = make_float2(0.f, 0.f);
            if (t > 0)
                dold = *(const float2*)&detT_old[j * 128 + mb];

            gates_pass(aR, aZ, aNi, g_hT, Wih_b, 16,
                       smem, sb, phG0, phG1, tid, mb, jl);
            if (t > 0)
                gates_pass(aR, aZ, aNh, detT_old, Whh_b, 32,
                           smem, sb, phG0, phG1, tid, mb, jl);

            float2 R = unpack2(aR), Z = unpack2(aZ);
            float2 Ni = unpack2(aNi), Nh = unpack2(aNh);
            float dn0, dn1;
            {
                float rr = 1.f / (1.f + expf(-(R.x + br)));
                float zz = 1.f / (1.f + expf(-(Z.x + bz)));
                float nn = tanhf(Ni.x + bin_ + rr * (Nh.x + bhn));
                dn0 = (1.f - zz) * nn + zz * dold.x;
            }
            {
                float rr = 1.f / (1.f + expf(-(R.y + br)));
                float zz = 1.f / (1.f + expf(-(Z.y + bz)));
                float nn = tanhf(Ni.y + bin_ + rr * (Nh.y + bhn));
                dn1 = (1.f - zz) * nn + zz * dold.y;
            }
            *(float2*)&detT_new[j * 128 + mb] = make_float2(dn0, dn1);
            dets[(size_t)mb * ldd + (size_t)t * DETER + j]       = dn0;
            dets[(size_t)(mb + 1) * ldd + (size_t)t * DETER + j] = dn1;
        }
        grid_sync();

        // ======================= P3: qh_T ==================================
        {
            const float po0 = pre_obs[((size_t)mb * T + t) * EMBED + n];
            const float po1 = pre_obs[((size_t)(mb + 1) * T + t) * EMBED + n];
            u64 acc = proj_pass(detT_new + g * 65536, Wq_b + g * 4096, 16,
                                smem, sb, abase, wbase, mbidx,
                                phP0, phP1, lt, mb, nl, gbar);
            if (g == 1) Red[slot] = acc;
            __syncthreads();
            if (g == 0) {
                float2 v = unpack2(acc);
                float2 r = unpack2(Red[slot]);
                float o0 = fmaxf(v.x + r.x + bq_n + po0, 0.f);
                float o1 = fmaxf(v.y + r.y + bq_n + po1, 0.f);
                *(float2*)&g_qhT[n * 128 + mb] = make_float2(o0, o1);
            }
        }
        grid_sync();
    }
}

// ---------------------------------------------------------------------------
// Host driver. Launch order puts level-2's level_kernel at launch index 5
// so ncu (-s 5 -c 1) finally profiles the scan kernel.
// ---------------------------------------------------------------------------
extern "C" void kernel_launch(void* const* d_in, const int* in_sizes, int n_in,
                              void* d_out, int out_size)
{
    (void)in_sizes; (void)n_in; (void)out_size;
    const float* obs_arr[3] = {
        (const float*)d_in[0], (const float*)d_in[1], (const float*)d_in[2] };
    const float* Wp  = (const float*)d_in[3];
    const float* bp  = (const float*)d_in[4];
    const float* Wih = (const float*)d_in[5];
    const float* Whh = (const float*)d_in[6];
    const float* bih = (const float*)d_in[7];
    const float* bhh = (const float*)d_in[8];
    const float* Wq  = (const float*)d_in[9];
    const float* bq  = (const float*)d_in[10];
    const float* Wqm = (const float*)d_in[11];
    const float* bqm = (const float*)d_in[12];

    float *d1_, *d2_, *pc_, *po_, *wc_;
    float *wih_d, *whh_d, *wq_d;
    cudaGetSymbolAddress((void**)&d1_, g_dets1);
    cudaGetSymbolAddress((void**)&d2_, g_dets2);
    cudaGetSymbolAddress((void**)&pc_, g_pre_ctx);
    cudaGetSymbolAddress((void**)&po_, g_pre_obs);
    cudaGetSymbolAddress((void**)&wc_, g_Wcomb);
    cudaGetSymbolAddress((void**)&wih_d, g_Wih_d);
    cudaGetSymbolAddress((void**)&whh_d, g_Whh_d);
    cudaGetSymbolAddress((void**)&wq_d,  g_Wq_d);

    static bool attr_set = false;
    if (!attr_set) {
        cudaFuncSetAttribute(level_kernel,
                             cudaFuncAttributeMaxDynamicSharedMemorySize,
                             SMEM_BYTES);
        attr_set = true;
    }

    const int Ts[3] = { T0, T0 / 4, T0 / 16 };   // 256, 64, 16
    float* dets[3]  = { (float*)d_out, d1_, d2_ };

    // #0: pack all static weights (all levels)
    pack_all_kernel<<<2048, 256>>>(Wih, Whh, Wq);

    for (int level = LVL - 1; level >= 0; level--) {
        const int T = Ts[level];
        const float* Wp_l  = Wp  + (size_t)level * (STOCH + DETER) * EMBED;
        const float* bp_l  = bp  + (size_t)level * EMBED;
        const float* bih_l = bih + (size_t)level * G3;
        const float* bhh_l = bhh + (size_t)level * G3;
        const float* Wq_l  = Wq  + (size_t)level * (DETER + OBS_D) * EMBED;
        const float* bq_l  = bq  + (size_t)level * EMBED;
        const float* Wqm_l = Wqm + (size_t)level * EMBED * STOCH;
        const float* bqm_l = bqm + (size_t)level * STOCH;

        // Wcomb = Wqm @ Wp_sample   (512x512, K=128)
        {
            dim3 gr(EMBED / 64, EMBED / 64);
            gemm64_kernel<<<gr, 128>>>(Wqm_l, STOCH, Wp_l, EMBED,
                                       wc_, EMBED, STOCH);
        }
        bvec_kernel<<<2, 256>>>(Wp_l, bp_l, bqm_l, level);
        pack_wc_kernel<<<512, 256>>>(wc_);

        const float* pre_ctx = nullptr;
        int T1 = 1;
        if (level < LVL - 1) {
            T1 = Ts[level + 1];
            dim3 gr(EMBED / 64, (BSZ * T1) / 64);
            gemm64_kernel<<<gr, 128>>>(
                dets[level + 1], DETER,
                Wp_l + (size_t)STOCH * EMBED, EMBED,
                pc_, EMBED, DETER);
            pre_ctx = pc_;
        }

        // pre_obs = obs @ Wq_obs  (K=512)
        {
            dim3 gr(EMBED / 64, (BSZ * T) / 64);
            gemm64_kernel<<<gr, 128>>>(
                obs_arr[level], OBS_D,
                Wq_l + (size_t)DETER * EMBED, EMBED,
                po_, EMBED, OBS_D);
        }

        level_kernel<<<NB, 512, SMEM_BYTES>>>(
            dets[level], T, pre_ctx, T1, po_,
            wih_d + (size_t)level * (512 * 1024 * 8),
            whh_d + (size_t)level * (1024 * 1024 * 8),
            wq_d  + (size_t)level * (1024 * 512 * 2),
            bih_l, bhh_l, bq_l, bp_l, level);
    }
}